// round 7
// baseline (speedup 1.0000x reference)
#include <cuda_runtime.h>
#include <math.h>

#define N_NODES 8192
#define MAXD 128
constexpr int KC = 32;   // GEMM k-chunk

// ---------------- scratch (device globals) ----------------------------------
__device__ __align__(16) float d_msg[N_NODES * 128];
__device__ __align__(16) float d_f  [N_NODES * 256];   // [unused | h]
__device__ float d_dinv[N_NODES];
__device__ int   d_cnt [N_NODES];
__device__ int   d_nbr [N_NODES * MAXD];

// ---------------- packed f32x2 helpers (PTX-only; ptxas never emits) --------
__device__ __forceinline__ unsigned long long f2pack(float lo, float hi) {
    unsigned long long r;
    asm("mov.b64 %0, {%1, %2};" : "=l"(r) : "f"(lo), "f"(hi));
    return r;
}
__device__ __forceinline__ void f2unpack(unsigned long long p, float& lo, float& hi) {
    asm("mov.b64 {%0, %1}, %2;" : "=f"(lo), "=f"(hi) : "l"(p));
}
__device__ __forceinline__ void ffma2(unsigned long long& d,
                                      unsigned long long a, unsigned long long b) {
    asm("fma.rn.f32x2 %0, %1, %2, %0;" : "+l"(d) : "l"(a), "l"(b));
}

// ---------------- per-row adjacency scan (2 batches of 4 float4) ------------
__device__ __forceinline__ void scan_row(const float* __restrict__ adj, int row)
{
    __shared__ int s_cnt;
    const int tid = threadIdx.x;
    if (tid == 0) s_cnt = 0;
    __syncthreads();

    const float4* a4 = (const float4*)(adj + (size_t)row * N_NODES);
    int* nbr = d_nbr + (size_t)row * MAXD;

#pragma unroll
    for (int half = 0; half < 2; half++) {
        float4 v[4];
#pragma unroll
        for (int u = 0; u < 4; u++)
            v[u] = __ldcs(&a4[tid + (half * 4 + u) * 256]);
#pragma unroll
        for (int u = 0; u < 4; u++) {
            const int base = (tid + (half * 4 + u) * 256) * 4;
            if (v[u].x != 0.f) { int p = atomicAdd(&s_cnt, 1); if (p < MAXD) nbr[p] = base + 0; }
            if (v[u].y != 0.f) { int p = atomicAdd(&s_cnt, 1); if (p < MAXD) nbr[p] = base + 1; }
            if (v[u].z != 0.f) { int p = atomicAdd(&s_cnt, 1); if (p < MAXD) nbr[p] = base + 2; }
            if (v[u].w != 0.f) { int p = atomicAdd(&s_cnt, 1); if (p < MAXD) nbr[p] = base + 3; }
        }
    }
    __syncthreads();
    if (tid == 0) {
        int cn = s_cnt;
        d_cnt[row]  = cn < MAXD ? cn : MAXD;
        d_dinv[row] = rsqrtf((float)cn + 1.0f);   // +1 self loop
    }
}

// ---------------- register-tiled GEMM with packed f32x2 FMA ------------------
// out = act(in_s @ W^T + b). Weight tile transposed+rotated (conflict-free).
template <int K, int M, bool RELU>
__device__ __forceinline__ void mlp_gemm(
        const float* in_s, int in_ss,
        const float* __restrict__ W, const float* __restrict__ bias,
        float* wt_s,
        float* out_s, int out_ss,
        float* out_g, int out_gs, int row0)
{
    constexpr int TX  = M / 4;
    constexpr int TY  = 256 / TX;
    constexpr int RPT = 32 / TY;
    constexpr int G   = M / 4;

    const int tid = threadIdx.x;
    const int tx  = tid % TX;
    const int ty  = tid / TX;

    unsigned long long acc01[RPT], acc23[RPT];
#pragma unroll
    for (int r = 0; r < RPT; r++) { acc01[r] = 0ull; acc23[r] = 0ull; }

    for (int k0 = 0; k0 < K; k0 += KC) {
        {   // weight tile, transposed + rotated
            int v = tid & 7;
#pragma unroll
            for (int m = tid >> 3; m < M; m += 32) {
                float4 w = *(const float4*)(W + (size_t)m * K + k0 + v * 4);
                int g = m >> 2, ml = m & 3;
                float wc[4] = {w.x, w.y, w.z, w.w};
#pragma unroll
                for (int c = 0; c < 4; c++) {
                    int k  = v * 4 + c;
                    int gp = (g + k + (k >> 2)) & (G - 1);
                    wt_s[k * M + gp * 4 + ml] = wc[c];
                }
            }
        }
        __syncthreads();

#pragma unroll
        for (int kv = 0; kv < KC / 4; kv++) {
            unsigned long long w01[4], w23[4];
#pragma unroll
            for (int c = 0; c < 4; c++) {
                int k  = kv * 4 + c;
                int gp = (tx + k + (k >> 2)) & (G - 1);
                float4 w = *(const float4*)&wt_s[k * M + gp * 4];
                w01[c] = f2pack(w.x, w.y);
                w23[c] = f2pack(w.z, w.w);
            }
#pragma unroll
            for (int rr = 0; rr < RPT; rr++) {
                float4 a = *(const float4*)&in_s[(ty * RPT + rr) * in_ss + k0 + kv * 4];
                unsigned long long aa;
                aa = f2pack(a.x, a.x); ffma2(acc01[rr], aa, w01[0]); ffma2(acc23[rr], aa, w23[0]);
                aa = f2pack(a.y, a.y); ffma2(acc01[rr], aa, w01[1]); ffma2(acc23[rr], aa, w23[1]);
                aa = f2pack(a.z, a.z); ffma2(acc01[rr], aa, w01[2]); ffma2(acc23[rr], aa, w23[2]);
                aa = f2pack(a.w, a.w); ffma2(acc01[rr], aa, w01[3]); ffma2(acc23[rr], aa, w23[3]);
            }
        }
        __syncthreads();
    }

    float4 bb = make_float4(0.f, 0.f, 0.f, 0.f);
    if (bias) bb = *(const float4*)(bias + tx * 4);

#pragma unroll
    for (int rr = 0; rr < RPT; rr++) {
        int r = ty * RPT + rr;
        float4 o;
        f2unpack(acc01[rr], o.x, o.y);
        f2unpack(acc23[rr], o.z, o.w);
        o.x += bb.x; o.y += bb.y; o.z += bb.z; o.w += bb.w;
        if (RELU) {
            o.x = fmaxf(o.x, 0.f); o.y = fmaxf(o.y, 0.f);
            o.z = fmaxf(o.z, 0.f); o.w = fmaxf(o.w, 0.f);
        }
        if (out_s) *(float4*)&out_s[r * out_ss + tx * 4] = o;
        if (out_g) *(float4*)(out_g + (size_t)(row0 + r) * out_gs + tx * 4) = o;
    }
}

// ---------------- fused: encoder blocks (0..255) + scan blocks (256..) ------
// min 5 blocks/SM (regs <= 51): scan path fits reg budget (4-float4 batches),
// encoder spill (rare blocks) hidden under the DRAM scan.
__global__ void __launch_bounds__(256, 5)
enc_scan_kernel(const float* __restrict__ x,
                const float* __restrict__ w1, const float* __restrict__ b1,
                const float* __restrict__ w2, const float* __restrict__ b2,
                const float* __restrict__ wg,
                float* __restrict__ f, float* __restrict__ msg,
                const float* __restrict__ adj)
{
    if ((int)blockIdx.x >= N_NODES / 32) {
        scan_row(adj, (int)blockIdx.x - N_NODES / 32);
        return;
    }

    extern __shared__ float esm[];
    float* s_a = esm;            // 4096: x tile, later h
    float* s_b = esm + 4096;     // 2048: h1
    float* wt  = esm + 6144;     // 4096: weight tile

    const int tid  = threadIdx.x;
    const int row0 = blockIdx.x * 32;

    {   // load x tile [32,32]
        int r = tid >> 3, vv = tid & 7;
        *(float4*)&s_a[r * 32 + vv * 4] =
            *(const float4*)(x + (size_t)(row0 + r) * 32 + vv * 4);
    }
    __syncthreads();

    mlp_gemm<32, 64, true>(s_a, 32, w1, b1, wt, s_b, 64, nullptr, 0, 0);
    __syncthreads();
    mlp_gemm<64, 128, true>(s_b, 64, w2, b2, wt, s_a, 128, f + 128, 256, row0);
    __syncthreads();
    mlp_gemm<128, 128, false>(s_a, 128, wg, nullptr, wt, nullptr, 0, msg, 128, row0);
}

// ---------------- fused decoder: agg -> wd -> wp1 -> wp2 -> wo*mask ---------
__global__ void __launch_bounds__(256, 3)
decoder_kernel(const float* __restrict__ msg, const float* __restrict__ bg,
               const float* __restrict__ wd,  const float* __restrict__ bd,
               const float* __restrict__ wp1, const float* __restrict__ bp1,
               const float* __restrict__ wp2, const float* __restrict__ bp2,
               const float* __restrict__ wo,  const float* __restrict__ bo,
               const float* __restrict__ mask,
               const float* __restrict__ f_g,
               float* __restrict__ out)
{
    extern __shared__ float sm[];
    float* s_f  = sm;            // [32][256]
    float* s_t  = sm + 8192;     // [32][128]: g, then p1
    float* wt   = sm + 12288;    // 4096: weight tile
    float* s_wo = sm + 16384;    // [8][64]
    float* s_bo = sm + 16896;    // [8]
    float* s_p2 = s_f;           // reuse after s_f dead

    const int tid  = threadIdx.x;
    const int row0 = blockIdx.x * 32;
    const int wid  = tid >> 5, lane = tid & 31;

    for (int i = tid; i < 32 * 32; i += 256) {   // h half of f
        int r = i >> 5, vv = i & 31;
        *(float4*)&s_f[r * 256 + 128 + vv * 4] =
            *(const float4*)(f_g + (size_t)(row0 + r) * 256 + 128 + vv * 4);
    }
    for (int i = tid; i < 512; i += 256) s_wo[i] = wo[i];
    if (tid < 8) s_bo[tid] = bo[tid];

    // ---- aggregation: g = relu(dinv_i*(dinv_i*msg_i + sum dj*msg_j) + bg) ----
    const float4 bg4 = *(const float4*)(bg + lane * 4);
#pragma unroll
    for (int t = 0; t < 4; t++) {
        const int row = row0 + wid + t * 8;
        const int cnt = d_cnt[row];
        const float di = d_dinv[row];

        float4 m0 = *(const float4*)(msg + (size_t)row * 128 + lane * 4);
        float4 a0 = make_float4(di * m0.x, di * m0.y, di * m0.z, di * m0.w);
        float4 a1 = make_float4(0.f, 0.f, 0.f, 0.f);
        float4 a2 = make_float4(0.f, 0.f, 0.f, 0.f);
        float4 a3 = make_float4(0.f, 0.f, 0.f, 0.f);

        for (int b = 0; b < cnt; b += 32) {
            int idx = 0; float dj = 0.f;
            if (b + lane < cnt) {
                idx = d_nbr[(size_t)row * MAXD + b + lane];
                dj  = d_dinv[idx];
            }
            const int mcnt = min(32, cnt - b);
            int u = 0;
            for (; u + 3 < mcnt; u += 4) {       // 4 gathers in flight
                int   j0 = __shfl_sync(0xffffffffu, idx, u);
                int   j1 = __shfl_sync(0xffffffffu, idx, u + 1);
                int   j2 = __shfl_sync(0xffffffffu, idx, u + 2);
                int   j3 = __shfl_sync(0xffffffffu, idx, u + 3);
                float w0 = __shfl_sync(0xffffffffu, dj, u);
                float w1 = __shfl_sync(0xffffffffu, dj, u + 1);
                float w2 = __shfl_sync(0xffffffffu, dj, u + 2);
                float w3 = __shfl_sync(0xffffffffu, dj, u + 3);
                float4 v0 = *(const float4*)(msg + (size_t)j0 * 128 + lane * 4);
                float4 v1 = *(const float4*)(msg + (size_t)j1 * 128 + lane * 4);
                float4 v2 = *(const float4*)(msg + (size_t)j2 * 128 + lane * 4);
                float4 v3 = *(const float4*)(msg + (size_t)j3 * 128 + lane * 4);
                a0.x += w0 * v0.x; a0.y += w0 * v0.y; a0.z += w0 * v0.z; a0.w += w0 * v0.w;
                a1.x += w1 * v1.x; a1.y += w1 * v1.y; a1.z += w1 * v1.z; a1.w += w1 * v1.w;
                a2.x += w2 * v2.x; a2.y += w2 * v2.y; a2.z += w2 * v2.z; a2.w += w2 * v2.w;
                a3.x += w3 * v3.x; a3.y += w3 * v3.y; a3.z += w3 * v3.z; a3.w += w3 * v3.w;
            }
            for (; u < mcnt; u++) {
                int   j0 = __shfl_sync(0xffffffffu, idx, u);
                float w0 = __shfl_sync(0xffffffffu, dj, u);
                float4 v0 = *(const float4*)(msg + (size_t)j0 * 128 + lane * 4);
                a0.x += w0 * v0.x; a0.y += w0 * v0.y; a0.z += w0 * v0.z; a0.w += w0 * v0.w;
            }
        }
        float4 g;
        g.x = fmaxf(di * ((a0.x + a1.x) + (a2.x + a3.x)) + bg4.x, 0.f);
        g.y = fmaxf(di * ((a0.y + a1.y) + (a2.y + a3.y)) + bg4.y, 0.f);
        g.z = fmaxf(di * ((a0.z + a1.z) + (a2.z + a3.z)) + bg4.z, 0.f);
        g.w = fmaxf(di * ((a0.w + a1.w) + (a2.w + a3.w)) + bg4.w, 0.f);
        *(float4*)&s_t[(row - row0) * 128 + lane * 4] = g;
    }
    __syncthreads();

    mlp_gemm<128, 128, true>(s_t, 128, wd, bd, wt, s_f, 256, nullptr, 0, 0);
    __syncthreads();
    mlp_gemm<256, 128, true>(s_f, 256, wp1, bp1, wt, s_t, 128, nullptr, 0, 0);
    __syncthreads();
    mlp_gemm<128, 64, true>(s_t, 128, wp2, bp2, wt, s_p2, 64, nullptr, 0, 0);
    __syncthreads();

    {   // out = (p2 @ wo^T + bo) * mask
        const int r = tid >> 3, m = tid & 7;
        float acc = 0.f;
#pragma unroll
        for (int k = 0; k < 64; k++) acc += s_p2[r * 64 + k] * s_wo[m * 64 + k];
        out[(size_t)(row0 + r) * 8 + m] = (acc + s_bo[m]) * mask[row0 + r];
    }
}

// ---------------- launch -----------------------------------------------------
extern "C" void kernel_launch(void* const* d_in, const int* in_sizes, int n_in,
                              void* d_out, int out_size)
{
    const float* x    = (const float*)d_in[0];
    const float* adj  = (const float*)d_in[1];
    const float* mask = (const float*)d_in[2];
    const float* w1   = (const float*)d_in[3];
    const float* b1   = (const float*)d_in[4];
    const float* w2   = (const float*)d_in[5];
    const float* b2   = (const float*)d_in[6];
    const float* wg   = (const float*)d_in[7];
    const float* bg   = (const float*)d_in[8];
    const float* wd   = (const float*)d_in[9];
    const float* bd   = (const float*)d_in[10];
    const float* wp1  = (const float*)d_in[11];
    const float* bp1  = (const float*)d_in[12];
    const float* wp2  = (const float*)d_in[13];
    const float* bp2  = (const float*)d_in[14];
    const float* wo   = (const float*)d_in[15];
    const float* bo   = (const float*)d_in[16];
    float* out = (float*)d_out;

    float *p_msg, *p_f;
    cudaGetSymbolAddress((void**)&p_msg, d_msg);
    cudaGetSymbolAddress((void**)&p_f,   d_f);

    const int ENC_SMEM = (4096 + 2048 + 4096) * 4;           // 40960 B
    const int DEC_SMEM = (8192 + 4096 + 4096 + 512 + 8) * 4; // 67616 B
    static int smem_set = 0;
    if (!smem_set) {
        cudaFuncSetAttribute(enc_scan_kernel,
                             cudaFuncAttributeMaxDynamicSharedMemorySize, ENC_SMEM);
        cudaFuncSetAttribute(decoder_kernel,
                             cudaFuncAttributeMaxDynamicSharedMemorySize, DEC_SMEM);
        smem_set = 1;
    }

    enc_scan_kernel<<<N_NODES / 32 + N_NODES, 256, ENC_SMEM>>>(
        x, w1, b1, w2, b2, wg, p_f, p_msg, adj);
    decoder_kernel<<<N_NODES / 32, 256, DEC_SMEM>>>(
        p_msg, bg, wd, bd, wp1, bp1, wp2, bp2, wo, bo, mask, p_f, out);
}